// round 1
// baseline (speedup 1.0000x reference)
#include <cuda_runtime.h>
#include <cuda_bf16.h>
#include <math.h>

// Problem constants
#define BATCH 2048      // B*T = 32*64
#define NAG   16        // agents
#define NACT  20        // actions
#define DDIM  128       // state dim
#define NSAMP 32        // S coalition samples
#define EDIM  64        // E
#define HDIM  256       // H
#define W1N   2560      // E*2*A

// ---------------- scratch (device globals, no allocation) ----------------
__device__ float g_h1a[BATCH * HDIM];     // relu(st@W1a+b1a)          2 MB
__device__ float g_hf [BATCH * HDIM];     // relu(st@Wfa+bfa)          2 MB
__device__ float g_w1 [BATCH * W1N];      // |h1a@W1b+b1b|            21 MB
__device__ float g_b1 [BATCH * EDIM];     // st@Wb+bb
__device__ float g_wf [BATCH * EDIM];     // |hf@Wfb+bfb|
__device__ float g_v  [BATCH];            // value head
__device__ float g_coal[BATCH * NAG * NACT];

// ---------------- generic fp32 SIMT GEMM: C = epi(A@B + bias) -------------
// A: MxK row-major, B: KxN row-major, bias: N, C: MxN
// Tile 128x64, BK=16, 256 threads, 8x4 microtile.
// EPI: 0 = none, 1 = relu, 2 = abs
template<int EPI>
__global__ void __launch_bounds__(256)
gemm_kernel(int M, int N, int K,
            const float* __restrict__ A,
            const float* __restrict__ B,
            const float* __restrict__ bias,
            float* __restrict__ C)
{
    __shared__ float As[16][132];   // pad 4 floats: keeps 16B align, kills STS conflicts
    __shared__ float Bs[16][64];

    const int tid = threadIdx.x;
    const int m0 = blockIdx.y * 128;
    const int n0 = blockIdx.x * 64;
    const int tx = tid & 15;   // 0..15 -> 4 cols
    const int ty = tid >> 4;   // 0..15 -> 8 rows

    float acc[8][4];
#pragma unroll
    for (int i = 0; i < 8; i++)
#pragma unroll
        for (int j = 0; j < 4; j++) acc[i][j] = 0.f;

    for (int k0 = 0; k0 < K; k0 += 16) {
        // A tile: 128x16 (2048 elems, 8/thread)
#pragma unroll
        for (int i = 0; i < 8; i++) {
            int idx = tid + i * 256;
            int m = idx >> 4, k = idx & 15;
            As[k][m] = A[(size_t)(m0 + m) * K + k0 + k];
        }
        // B tile: 16x64 (1024 elems, 4/thread)
#pragma unroll
        for (int i = 0; i < 4; i++) {
            int idx = tid + i * 256;
            int k = idx >> 6, n = idx & 63;
            Bs[k][n] = B[(size_t)(k0 + k) * N + n0 + n];
        }
        __syncthreads();
#pragma unroll
        for (int kk = 0; kk < 16; kk++) {
            float4 a0 = *(const float4*)&As[kk][ty * 8];
            float4 a1 = *(const float4*)&As[kk][ty * 8 + 4];
            float4 bv = *(const float4*)&Bs[kk][tx * 4];
            float av[8] = {a0.x, a0.y, a0.z, a0.w, a1.x, a1.y, a1.z, a1.w};
            float bw[4] = {bv.x, bv.y, bv.z, bv.w};
#pragma unroll
            for (int i = 0; i < 8; i++)
#pragma unroll
                for (int j = 0; j < 4; j++)
                    acc[i][j] += av[i] * bw[j];
        }
        __syncthreads();
    }

    float bs[4];
#pragma unroll
    for (int j = 0; j < 4; j++) bs[j] = bias[n0 + tx * 4 + j];

#pragma unroll
    for (int i = 0; i < 8; i++) {
        int m = m0 + ty * 8 + i;
        float4 o;
        float* po = &o.x;
#pragma unroll
        for (int j = 0; j < 4; j++) {
            float c = acc[i][j] + bs[j];
            if (EPI == 1) c = fmaxf(c, 0.f);
            if (EPI == 2) c = fabsf(c);
            po[j] = c;
        }
        *(float4*)&C[(size_t)m * N + n0 + tx * 4] = o;
    }
}

// ---------------- value head: v[b] = relu(st@Wv1+bv1)@Wv2 + bv2 -----------
__global__ void __launch_bounds__(64)
v_kernel(const float* __restrict__ states,
         const float* __restrict__ Wv1, const float* __restrict__ bv1,
         const float* __restrict__ Wv2, const float* __restrict__ bv2,
         float* __restrict__ v)
{
    int b = blockIdx.x;
    int e = threadIdx.x;  // 64
    __shared__ float st[DDIM];
    st[e] = states[b * DDIM + e];
    st[e + 64] = states[b * DDIM + 64 + e];
    __syncthreads();
    float acc = bv1[e];
#pragma unroll 8
    for (int d = 0; d < DDIM; d++)
        acc += st[d] * Wv1[d * EDIM + e];
    float p = fmaxf(acc, 0.f) * Wv2[e];
#pragma unroll
    for (int o = 16; o > 0; o >>= 1)
        p += __shfl_down_sync(0xffffffffu, p, o);
    __shared__ float r[2];
    if ((e & 31) == 0) r[e >> 5] = p;
    __syncthreads();
    if (e == 0) v[b] = r[0] + r[1] + bv2[0];
}

// ---------------- coalition kernel ----------------------------------------
// coal[b,i,a] = (1/(16*32)) * sum_s gc[b,s,i] * Q[b,s,gc[b,s,i]][a]
// Q[m][a] = sum_{j<m} actions[b, gc[b,s,j], a]   (prefix over permutation pos)
__global__ void __launch_bounds__(320)
coal_kernel(const float* __restrict__ actions,
            const int* __restrict__ gc,
            float* __restrict__ coal)
{
    int b = blockIdx.x;
    int tid = threadIdx.x;              // 320 = 16*20
    int i = tid / NACT, a = tid % NACT;

    __shared__ float act_s[NAG][NACT];
    __shared__ int   gcs[NSAMP][NAG];
    __shared__ float S[NAG][NACT];
    __shared__ float Q[NAG][NACT];

    act_s[i][a] = actions[b * NAG * NACT + tid];
    for (int idx = tid; idx < NSAMP * NAG; idx += 320)
        ((int*)gcs)[idx] = gc[b * NSAMP * NAG + idx];
    __syncthreads();

    float acc = 0.f;
    for (int s = 0; s < NSAMP; s++) {
        S[i][a] = act_s[gcs[s][i]][a];
        __syncthreads();
        float q = 0.f;
        for (int j = 0; j < i; j++) q += S[j][a];
        Q[i][a] = q;
        __syncthreads();
        int g = gcs[s][i];
        acc += (float)g * Q[g][a];
        __syncthreads();
    }
    coal[b * NAG * NACT + i * NACT + a] = acc * (1.f / (16.f * 32.f));
}

// ---------------- final mix ------------------------------------------------
// hidden[i,e] = elu( sum_{k<40} inputs[i,k]*w1[k,e] + b1[e] )
// y[i] = sum_e hidden*wf[e] + v ; w_est = |y| ; q_tot = sum_i w_est*aq
__global__ void __launch_bounds__(1024)
final_kernel(const float* __restrict__ w1, const float* __restrict__ coal,
             const float* __restrict__ actions, const float* __restrict__ b1,
             const float* __restrict__ wf, const float* __restrict__ v,
             const float* __restrict__ agent_qs,
             float* __restrict__ q_out, float* __restrict__ w_out)
{
    int b = blockIdx.x;
    int tid = threadIdx.x;          // 1024 = 16*64
    int i = tid >> 6, e = tid & 63;

    __shared__ float w1s[40][EDIM];     // 10 KB
    __shared__ float ins[NAG][40];      // concat(coal, act)
    __shared__ float wfs[EDIM], b1s[EDIM];
    __shared__ float red[32];
    __shared__ float qpart[NAG];

    for (int idx = tid; idx < W1N; idx += 1024)
        ((float*)w1s)[idx] = w1[(size_t)b * W1N + idx];
    if (tid < 320)
        ins[tid / NACT][tid % NACT] = coal[b * NAG * NACT + tid];
    else if (tid < 640) {
        int t = tid - 320;
        ins[t / NACT][NACT + t % NACT] = actions[b * NAG * NACT + t];
    } else if (tid < 704) {
        wfs[tid - 640] = wf[b * EDIM + tid - 640];
    } else if (tid < 768) {
        b1s[tid - 704] = b1[b * EDIM + tid - 704];
    }
    __syncthreads();

    float h = b1s[e];
#pragma unroll
    for (int k = 0; k < 40; k++)
        h += ins[i][k] * w1s[k][e];
    float hid = h > 0.f ? h : expm1f(h);
    float p = hid * wfs[e];
#pragma unroll
    for (int o = 16; o > 0; o >>= 1)
        p += __shfl_down_sync(0xffffffffu, p, o);
    if ((tid & 31) == 0) red[tid >> 5] = p;
    __syncthreads();
    if (e == 0) {
        float y = red[i * 2] + red[i * 2 + 1] + v[b];
        float w = fabsf(y);
        if (w_out) w_out[b * NAG + i] = w;
        qpart[i] = w * agent_qs[b * NAG + i];
    }
    __syncthreads();
    if (tid == 0 && q_out) {
        float q = 0.f;
#pragma unroll
        for (int ii = 0; ii < NAG; ii++) q += qpart[ii];
        q_out[b] = q;
    }
}

// ---------------- launch ---------------------------------------------------
extern "C" void kernel_launch(void* const* d_in, const int* in_sizes, int n_in,
                              void* d_out, int out_size)
{
    const float* states    = (const float*)d_in[0];
    const float* actions   = (const float*)d_in[1];
    const float* agent_qs  = (const float*)d_in[2];
    // d_in[3] = max_filter (unused)
    const int*   gc        = (const int*)  d_in[4];
    const float* W1a = (const float*)d_in[5];
    const float* b1a = (const float*)d_in[6];
    const float* W1b = (const float*)d_in[7];
    const float* b1b = (const float*)d_in[8];
    const float* Wb  = (const float*)d_in[9];
    const float* bb  = (const float*)d_in[10];
    const float* Wfa = (const float*)d_in[11];
    const float* bfa = (const float*)d_in[12];
    const float* Wfb = (const float*)d_in[13];
    const float* bfb = (const float*)d_in[14];
    const float* Wv1 = (const float*)d_in[15];
    const float* bv1 = (const float*)d_in[16];
    const float* Wv2 = (const float*)d_in[17];
    const float* bv2 = (const float*)d_in[18];

    static float *p_h1a = nullptr, *p_hf, *p_w1, *p_b1, *p_wf, *p_v, *p_coal;
    if (!p_h1a) {
        cudaGetSymbolAddress((void**)&p_h1a,  g_h1a);
        cudaGetSymbolAddress((void**)&p_hf,   g_hf);
        cudaGetSymbolAddress((void**)&p_w1,   g_w1);
        cudaGetSymbolAddress((void**)&p_b1,   g_b1);
        cudaGetSymbolAddress((void**)&p_wf,   g_wf);
        cudaGetSymbolAddress((void**)&p_v,    g_v);
        cudaGetSymbolAddress((void**)&p_coal, g_coal);
    }

    float* out = (float*)d_out;
    float* q_out = nullptr;
    float* w_out = nullptr;
    if (out_size == BATCH + BATCH * NAG)      { q_out = out; w_out = out + BATCH; }
    else if (out_size == BATCH * NAG)         { w_out = out; }
    else if (out_size == BATCH)               { q_out = out; }
    else                                      { q_out = out; w_out = out + BATCH; }

    // h1a = relu(states @ W1a + b1a)          [2048 x 256], K=128
    gemm_kernel<1><<<dim3(HDIM / 64, BATCH / 128), 256>>>(BATCH, HDIM, DDIM, states, W1a, b1a, p_h1a);
    // hf  = relu(states @ Wfa + bfa)          [2048 x 256], K=128
    gemm_kernel<1><<<dim3(HDIM / 64, BATCH / 128), 256>>>(BATCH, HDIM, DDIM, states, Wfa, bfa, p_hf);
    // b1  = states @ Wb + bb                  [2048 x 64],  K=128
    gemm_kernel<0><<<dim3(EDIM / 64, BATCH / 128), 256>>>(BATCH, EDIM, DDIM, states, Wb, bb, p_b1);
    // wf  = |hf @ Wfb + bfb|                  [2048 x 64],  K=256
    gemm_kernel<2><<<dim3(EDIM / 64, BATCH / 128), 256>>>(BATCH, EDIM, HDIM, p_hf, Wfb, bfb, p_wf);
    // w1  = |h1a @ W1b + b1b|                 [2048 x 2560], K=256  (dominant)
    gemm_kernel<2><<<dim3(W1N / 64, BATCH / 128), 256>>>(BATCH, W1N, HDIM, p_h1a, W1b, b1b, p_w1);
    // value head
    v_kernel<<<BATCH, 64>>>(states, Wv1, bv1, Wv2, bv2, p_v);
    // coalition inputs
    coal_kernel<<<BATCH, 320>>>(actions, gc, p_coal);
    // final fused mix
    final_kernel<<<BATCH, 1024>>>(p_w1, p_coal, actions, p_b1, p_wf, p_v,
                                  agent_qs, q_out, w_out);
}